// round 7
// baseline (speedup 1.0000x reference)
#include <cuda_runtime.h>
#include <math.h>

#define NL 10000
#define NP 100000
#define PL 8
#define HH 32
#define NROUNDS 8

// Scratch state (no allocations allowed)
__device__ __align__(256) float g_link_state[NL * HH];
__device__ __align__(256) float g_path_state[NP * HH];
__device__ __align__(256) float g_agg[NL * HH];
// Per-link input-side projection, biases folded.
// Layout per link (96 floats): [0:32) = Z_j ; [32:96) = interleaved (R_j, N_j) pairs.
__device__ __align__(256) float g_proj[NL * 96];

__device__ __forceinline__ float sigf(float v) { return 1.0f / (1.0f + expf(-v)); }

// Fast activations (hot kernels). __expf error ~2^-21 rel.
__device__ __forceinline__ float fsig(float v) {
    return __fdividef(1.0f, 1.0f + __expf(-v));
}
__device__ __forceinline__ float ftanh(float v) {
    float e = __expf(-2.0f * fabsf(v));
    float t = __fdividef(1.0f - e, 1.0f + e);
    return copysignf(t, v);
}

// Packed fp32x2 helpers (sm_100+). Bit-exact fp32 FMA semantics, 2 lanes/instr.
#define PACKF2(out, lo, hi) \
    asm("mov.b64 %0, {%1, %2};" : "=l"(out) : "r"(__float_as_uint(lo)), "r"(__float_as_uint(hi)))
#define UNPACKF2(lo, hi, in) \
    do { unsigned int _ul, _uh; \
         asm("mov.b64 {%0, %1}, %2;" : "=r"(_ul), "=r"(_uh) : "l"(in)); \
         lo = __uint_as_float(_ul); hi = __uint_as_float(_uh); } while (0)
#define FMAF2(d, a, b, c) \
    asm("fma.rn.f32x2 %0, %1, %2, %3;" : "=l"(d) : "l"(a), "l"(b), "l"(c))

// ---------------------------------------------------------------------------
// Init
// ---------------------------------------------------------------------------
__global__ void init_kernel(const float* __restrict__ cap, const float* __restrict__ bw) {
    int i = blockIdx.x * blockDim.x + threadIdx.x;
    if (i < NL * HH) {
        g_link_state[i] = ((i & 31) == 0) ? cap[i >> 5] : 0.0f;
        g_agg[i] = 0.0f;
    }
    if (i < NP * HH) {
        g_path_state[i] = ((i & 31) == 0) ? bw[i >> 5] : 0.0f;
    }
}

// ---------------------------------------------------------------------------
// Projection kernel: proj[link] = Wih @ link_state[link] with biases folded.
// One warp per link, lane j computes (Z_j, R_j, N_j).
// ---------------------------------------------------------------------------
#define NT_PROJ 256

__global__ void __launch_bounds__(NT_PROJ) proj_kernel(
    const float* __restrict__ Wih, const float* __restrict__ bih,
    const float* __restrict__ bhh)
{
    __shared__ float sWih[3072];
    __shared__ float sb[192];
    const int tid = threadIdx.x;
    for (int i = tid; i < 3072; i += NT_PROJ) sWih[i] = Wih[i];
    if (tid < 96) { sb[tid] = bih[tid]; sb[96 + tid] = bhh[tid]; }
    __syncthreads();

    const int gid = blockIdx.x * NT_PROJ + tid;
    const int link = gid >> 5;
    const int j = gid & 31;
    if (link >= NL) return;

    float x[32];
    {
        const float4* xp = (const float4*)(g_link_state + (size_t)link * 32);
#pragma unroll
        for (int k = 0; k < 8; k++) {
            float4 v = xp[k];
            x[4*k] = v.x; x[4*k+1] = v.y; x[4*k+2] = v.z; x[4*k+3] = v.w;
        }
    }

#define DOTX(ROW, OUT)                                                                  \
    do {                                                                                \
        const float4* wi_ = (const float4*)(sWih + (ROW) * 32);                         \
        float s0 = 0.f, s1 = 0.f, s2 = 0.f, s3 = 0.f;                                   \
        _Pragma("unroll")                                                               \
        for (int k_ = 0; k_ < 2; k_++) {                                                \
            float4 a = wi_[4*k_+0], b = wi_[4*k_+1], c = wi_[4*k_+2], d = wi_[4*k_+3];  \
            s0 = fmaf(a.x, x[16*k_+ 0], s0); s0 = fmaf(a.y, x[16*k_+ 1], s0);           \
            s0 = fmaf(a.z, x[16*k_+ 2], s0); s0 = fmaf(a.w, x[16*k_+ 3], s0);           \
            s1 = fmaf(b.x, x[16*k_+ 4], s1); s1 = fmaf(b.y, x[16*k_+ 5], s1);           \
            s1 = fmaf(b.z, x[16*k_+ 6], s1); s1 = fmaf(b.w, x[16*k_+ 7], s1);           \
            s2 = fmaf(c.x, x[16*k_+ 8], s2); s2 = fmaf(c.y, x[16*k_+ 9], s2);           \
            s2 = fmaf(c.z, x[16*k_+10], s2); s2 = fmaf(c.w, x[16*k_+11], s2);           \
            s3 = fmaf(d.x, x[16*k_+12], s3); s3 = fmaf(d.y, x[16*k_+13], s3);           \
            s3 = fmaf(d.z, x[16*k_+14], s3); s3 = fmaf(d.w, x[16*k_+15], s3);           \
        }                                                                               \
        OUT = (s0 + s1) + (s2 + s3);                                                    \
    } while (0)

    float dz, dr, dn;
    DOTX(32 + j, dz);
    DOTX(j, dr);
    DOTX(64 + j, dn);
#undef DOTX

    float* pp = g_proj + (size_t)link * 96;
    pp[j]             = dz + sb[32 + j] + sb[128 + j];
    pp[32 + 2*j]      = dr + sb[j] + sb[96 + j];
    pp[32 + 2*j + 1]  = dn + sb[64 + j];
}

// ---------------------------------------------------------------------------
// Path kernel (R7): warp-per-path, lane = feature.
//  - next-hop proj prefetched at hop start (overlaps the dot chain)
//  - h staged PRE-PACKED: even lanes store (h2k,h2k+1) pairs, dot loop reads
//    ulonglong2 -> no per-hop re-packing
//  - hidden-side dots with packed fma.rn.f32x2 (weights pre-packed in regs)
// ---------------------------------------------------------------------------
#define NT_PATH 256
#define PATH_BLOCKS 592

__global__ void __launch_bounds__(NT_PATH, 2) path_kernel(
    const int* __restrict__ links,
    const float* __restrict__ Whh, const float* __restrict__ bhh)
{
    __shared__ __align__(16) unsigned long long sP[2][NT_PATH / 2];  // packed h pairs

    const int lane = threadIdx.x & 31;
    const int wbase = threadIdx.x & ~31;         // warp*32
    const int warp_global = (blockIdx.x * (NT_PATH / 32)) + (threadIdx.x >> 5);
    const int n_warps = gridDim.x * (NT_PATH / 32);

    // Pre-packed weight pairs: Wz2[k] = (Wz[2k], Wz[2k+1]) etc.
    unsigned long long Wz2[16], Wr2[16], Wn2[16];
    {
        const float2* wz = (const float2*)(Whh + (size_t)(32 + lane) * 32);
        const float2* wr = (const float2*)(Whh + (size_t)lane * 32);
        const float2* wn = (const float2*)(Whh + (size_t)(64 + lane) * 32);
#pragma unroll
        for (int k = 0; k < 16; k++) {
            float2 a = wz[k]; PACKF2(Wz2[k], a.x, a.y);
            float2 b = wr[k]; PACKF2(Wr2[k], b.x, b.y);
            float2 c = wn[k]; PACKF2(Wn2[k], c.x, c.y);
        }
    }
    const float bn = bhh[64 + lane];
    const int pslot = (wbase >> 1) + (lane >> 1);

    for (int p = warp_global; p < NP; p += n_warps) {
        float h = g_path_state[(size_t)p * 32 + lane];
        int links8 = (lane < 8) ? links[(size_t)p * 8 + lane] : 0;

        // Preload hop 0 proj
        int link = __shfl_sync(0xffffffffu, links8, 0);
        const float* pp = g_proj + (size_t)link * 96;
        float Zp = pp[lane];
        float2 RN = *(const float2*)(pp + 32 + 2 * lane);

#pragma unroll
        for (int t = 0; t < PL; t++) {
            // Stage packed h pairs (even lanes store (h_j, h_{j+1}))
            const int par = t & 1;
            const float hnb = __shfl_down_sync(0xffffffffu, h, 1);
            unsigned long long hp_;
            PACKF2(hp_, h, hnb);
            if (!(lane & 1)) sP[par][pslot] = hp_;
            __syncwarp();

            // Prefetch next hop's proj (independent of h -> overlaps dot chain)
            int link_n = 0; float Zp_n = 0.f; float2 RN_n = make_float2(0.f, 0.f);
            if (t < PL - 1) {
                link_n = __shfl_sync(0xffffffffu, links8, t + 1);
                const float* ppn = g_proj + (size_t)link_n * 96;
                Zp_n = ppn[lane];
                RN_n = *(const float2*)(ppn + 32 + 2 * lane);
            }

            const ulonglong2* hv = (const ulonglong2*)&sP[par][wbase >> 1];
            unsigned long long az2 = 0ull, ar2 = 0ull, an2 = 0ull;
#pragma unroll
            for (int kk = 0; kk < 8; kk++) {
                ulonglong2 hq = hv[kk];              // broadcast LDS.128 -> 2 packed pairs
                FMAF2(az2, Wz2[2*kk],   hq.x, az2);
                FMAF2(az2, Wz2[2*kk+1], hq.y, az2);
                FMAF2(ar2, Wr2[2*kk],   hq.x, ar2);
                FMAF2(ar2, Wr2[2*kk+1], hq.y, ar2);
                FMAF2(an2, Wn2[2*kk],   hq.x, an2);
                FMAF2(an2, Wn2[2*kk+1], hq.y, an2);
            }
            float azl, azh, arl, arh, anl, anh;
            UNPACKF2(azl, azh, az2);
            UNPACKF2(arl, arh, ar2);
            UNPACKF2(anl, anh, an2);

            const float z = fsig(Zp + (azl + azh));
            const float r = fsig(RN.x + (arl + arh));
            const float n = ftanh(RN.y + r * ((anl + anh) + bn));
            h = fmaf(z, h - n, n);                   // h' = n + z*(h-n)
            atomicAdd(g_agg + (size_t)link * 32 + lane, h);   // 1 coalesced line

            link = link_n; Zp = Zp_n; RN = RN_n;
        }

        g_path_state[(size_t)p * 32 + lane] = h;
    }
}

// ---------------------------------------------------------------------------
// Link kernel (R7): warp-per-link, lane = feature j.
// Full x/h copies in registers (broadcast loads); weights in shared
// TRANSPOSED: sWT[k*192 + row] -> per-lane row reads are conflict-free.
// Rows: [0:32)=Wih_r [32:64)=Wih_z [64:96)=Wih_n [96:128)=Whh_r
//       [128:160)=Whh_z [160:192)=Whh_n
// ---------------------------------------------------------------------------
#define NT_LINK2 256

__global__ void __launch_bounds__(NT_LINK2) link_kernel(
    const float* __restrict__ Wih, const float* __restrict__ Whh,
    const float* __restrict__ bih, const float* __restrict__ bhh)
{
    __shared__ float sWT[32 * 192];   // 24 KB
    __shared__ float sb[192];

    const int tid = threadIdx.x;
    for (int i = tid; i < 3072; i += NT_LINK2) {
        int row = i >> 5, k = i & 31;
        sWT[k * 192 + row]       = Wih[i];
        sWT[k * 192 + 96 + row]  = Whh[i];
    }
    if (tid < 96) { sb[tid] = bih[tid]; sb[96 + tid] = bhh[tid]; }
    __syncthreads();

    const int gid = blockIdx.x * NT_LINK2 + tid;
    const int link = gid >> 5;
    const int j = gid & 31;
    if (link >= NL) return;

    // Full broadcast copies of x (agg) and h (link_state)
    float x[32], h[32];
    {
        const float4* xp = (const float4*)(g_agg + (size_t)link * 32);
        const float4* hp = (const float4*)(g_link_state + (size_t)link * 32);
#pragma unroll
        for (int k = 0; k < 8; k++) {
            float4 u = xp[k];
            x[4*k] = u.x; x[4*k+1] = u.y; x[4*k+2] = u.z; x[4*k+3] = u.w;
            float4 v = hp[k];
            h[4*k] = v.x; h[4*k+1] = v.y; h[4*k+2] = v.z; h[4*k+3] = v.w;
        }
    }

    float dr = 0.f, dz = 0.f, dn = 0.f;   // input-side dots
    float er = 0.f, ez = 0.f, en = 0.f;   // hidden-side dots
#pragma unroll
    for (int k = 0; k < 32; k++) {
        const float* w = sWT + k * 192;
        dr = fmaf(w[j],        x[k], dr);
        dz = fmaf(w[32 + j],   x[k], dz);
        dn = fmaf(w[64 + j],   x[k], dn);
        er = fmaf(w[96 + j],   h[k], er);
        ez = fmaf(w[128 + j],  h[k], ez);
        en = fmaf(w[160 + j],  h[k], en);
    }

    const float z = fsig(dz + sb[32 + j] + ez + sb[128 + j]);
    const float r = fsig(dr + sb[j] + er + sb[96 + j]);
    const float n = ftanh(dn + sb[64 + j] + r * (en + sb[160 + j]));
    const float hn = fmaf(z, h[j] - n, n);

    g_link_state[(size_t)link * 32 + j] = hn;   // coalesced
    g_agg[(size_t)link * 32 + j] = 0.0f;        // clear for next round
}

// ---------------------------------------------------------------------------
// Readout MLP: 32 -> relu 8 -> relu 8 -> 1
// ---------------------------------------------------------------------------
__global__ void __launch_bounds__(128) readout_kernel(
    const float* __restrict__ W1, const float* __restrict__ b1,
    const float* __restrict__ W2, const float* __restrict__ b2,
    const float* __restrict__ W3, const float* __restrict__ b3,
    float* __restrict__ out)
{
    __shared__ float sW1[256], sW2[64], sW3[8], sb1[8], sb2[8], sb3;
    int tid = threadIdx.x;
    for (int i = tid; i < 256; i += 128) sW1[i] = W1[i];
    if (tid < 64) sW2[tid] = W2[tid];
    if (tid < 8) { sW3[tid] = W3[tid]; sb1[tid] = b1[tid]; sb2[tid] = b2[tid]; }
    if (tid == 0) sb3 = b3[0];
    __syncthreads();

    int p = blockIdx.x * 128 + tid;
    if (p >= NP) return;

    float x[32];
    const float4* hp = (const float4*)(g_path_state + (size_t)p * 32);
#pragma unroll
    for (int k = 0; k < 8; k++) {
        float4 v = hp[k];
        x[4*k] = v.x; x[4*k+1] = v.y; x[4*k+2] = v.z; x[4*k+3] = v.w;
    }
    float y[8];
#pragma unroll
    for (int j = 0; j < 8; j++) {
        float s = sb1[j];
#pragma unroll
        for (int k = 0; k < 32; k++) s = fmaf(sW1[j * 32 + k], x[k], s);
        y[j] = fmaxf(s, 0.0f);
    }
    float y2[8];
#pragma unroll
    for (int j = 0; j < 8; j++) {
        float s = sb2[j];
#pragma unroll
        for (int k = 0; k < 8; k++) s = fmaf(sW2[j * 8 + k], y[k], s);
        y2[j] = fmaxf(s, 0.0f);
    }
    float s = sb3;
#pragma unroll
    for (int k = 0; k < 8; k++) s = fmaf(sW3[k], y2[k], s);
    out[p] = s;
}

// ---------------------------------------------------------------------------
extern "C" void kernel_launch(void* const* d_in, const int* in_sizes, int n_in,
                              void* d_out, int out_size)
{
    const int*   links = (const int*)d_in[0];
    // d_in[1]=paths, d_in[2]=seqs: layout is paths=repeat, seqs=tile -> hop(p,t)=links[8p+t]
    const float* cap   = (const float*)d_in[3];
    const float* bw    = (const float*)d_in[4];
    const float* pWih  = (const float*)d_in[5];
    const float* pWhh  = (const float*)d_in[6];
    const float* pbih  = (const float*)d_in[7];
    const float* pbhh  = (const float*)d_in[8];
    const float* lWih  = (const float*)d_in[9];
    const float* lWhh  = (const float*)d_in[10];
    const float* lbih  = (const float*)d_in[11];
    const float* lbhh  = (const float*)d_in[12];
    const float* W1    = (const float*)d_in[13];
    const float* b1    = (const float*)d_in[14];
    const float* W2    = (const float*)d_in[15];
    const float* b2    = (const float*)d_in[16];
    const float* W3    = (const float*)d_in[17];
    const float* b3    = (const float*)d_in[18];
    float* out = (float*)d_out;

    init_kernel<<<(NP * HH + 255) / 256, 256>>>(cap, bw);

    const int link_blocks = (NL * 32 + NT_LINK2 - 1) / NT_LINK2;
    const int proj_blocks = (NL * 32 + NT_PROJ - 1) / NT_PROJ;
    for (int r = 0; r < NROUNDS; r++) {
        proj_kernel<<<proj_blocks, NT_PROJ>>>(pWih, pbih, pbhh);
        path_kernel<<<PATH_BLOCKS, NT_PATH>>>(links, pWhh, pbhh);
        if (r < NROUNDS - 1)  // final link update is dead code (readout uses path_state)
            link_kernel<<<link_blocks, NT_LINK2>>>(lWih, lWhh, lbih, lbhh);
    }
    readout_kernel<<<(NP + 127) / 128, 128>>>(W1, b1, W2, b2, W3, b3, out);
}

// round 8
// speedup vs baseline: 1.1052x; 1.1052x over previous
#include <cuda_runtime.h>
#include <math.h>

#define NL 10000
#define NP 100000
#define PL 8
#define HH 32
#define NROUNDS 8

// Scratch state (no allocations allowed)
__device__ __align__(256) float g_link_state[NL * HH];
__device__ __align__(256) float g_path_state[NP * HH];
__device__ __align__(256) float g_agg[NL * HH];
// Per-link input-side projection, biases folded.
// Layout per link (96 floats): [0:32) = Z_j ; [32:96) = interleaved (R_j, N_j) pairs.
__device__ __align__(256) float g_proj[NL * 96];

// Fast activations. __expf error ~2^-21 rel; far inside 1e-3 budget.
__device__ __forceinline__ float fsig(float v) {
    return __fdividef(1.0f, 1.0f + __expf(-v));
}
__device__ __forceinline__ float ftanh(float v) {
    float e = __expf(-2.0f * fabsf(v));
    float t = __fdividef(1.0f - e, 1.0f + e);
    return copysignf(t, v);
}

// Packed fp32x2 helpers (sm_100+). Bit-exact fp32 FMA semantics, 2 lanes/instr.
#define PACKF2(out, lo, hi) \
    asm("mov.b64 %0, {%1, %2};" : "=l"(out) : "r"(__float_as_uint(lo)), "r"(__float_as_uint(hi)))
#define UNPACKF2(lo, hi, in) \
    do { unsigned int _ul, _uh; \
         asm("mov.b64 {%0, %1}, %2;" : "=r"(_ul), "=r"(_uh) : "l"(in)); \
         lo = __uint_as_float(_ul); hi = __uint_as_float(_uh); } while (0)
#define FMAF2(d, a, b, c) \
    asm("fma.rn.f32x2 %0, %1, %2, %3;" : "=l"(d) : "l"(a), "l"(b), "l"(c))

// ---------------------------------------------------------------------------
// Init
// ---------------------------------------------------------------------------
__global__ void init_kernel(const float* __restrict__ cap, const float* __restrict__ bw) {
    int i = blockIdx.x * blockDim.x + threadIdx.x;
    if (i < NL * HH) {
        g_link_state[i] = ((i & 31) == 0) ? cap[i >> 5] : 0.0f;
        g_agg[i] = 0.0f;
    }
    if (i < NP * HH) {
        g_path_state[i] = ((i & 31) == 0) ? bw[i >> 5] : 0.0f;
    }
}

// ---------------------------------------------------------------------------
// Projection kernel (round 0 only): proj[link] = Wih @ link_state + biases.
//   Z_j = bih[32+j]+bhh[32+j] + dot(Wih_z_j, x)
//   R_j = bih[j]   +bhh[j]    + dot(Wih_r_j, x)
//   N_j = bih[64+j]           + dot(Wih_n_j, x)   (bhh_n applied in path kernel)
// ---------------------------------------------------------------------------
#define NT_PROJ 256

__global__ void __launch_bounds__(NT_PROJ) proj_kernel(
    const float* __restrict__ Wih, const float* __restrict__ bih,
    const float* __restrict__ bhh)
{
    __shared__ float sWih[3072];
    __shared__ float sb[192];
    const int tid = threadIdx.x;
    for (int i = tid; i < 3072; i += NT_PROJ) sWih[i] = Wih[i];
    if (tid < 96) { sb[tid] = bih[tid]; sb[96 + tid] = bhh[tid]; }
    __syncthreads();

    const int gid = blockIdx.x * NT_PROJ + tid;
    const int link = gid >> 5;
    const int j = gid & 31;
    if (link >= NL) return;

    float x[32];
    {
        const float4* xp = (const float4*)(g_link_state + (size_t)link * 32);
#pragma unroll
        for (int k = 0; k < 8; k++) {
            float4 v = xp[k];
            x[4*k] = v.x; x[4*k+1] = v.y; x[4*k+2] = v.z; x[4*k+3] = v.w;
        }
    }

#define DOTX(ROW, OUT)                                                                  \
    do {                                                                                \
        const float4* wi_ = (const float4*)(sWih + (ROW) * 32);                         \
        float s0 = 0.f, s1 = 0.f, s2 = 0.f, s3 = 0.f;                                   \
        _Pragma("unroll")                                                               \
        for (int k_ = 0; k_ < 2; k_++) {                                                \
            float4 a = wi_[4*k_+0], b = wi_[4*k_+1], c = wi_[4*k_+2], d = wi_[4*k_+3];  \
            s0 = fmaf(a.x, x[16*k_+ 0], s0); s0 = fmaf(a.y, x[16*k_+ 1], s0);           \
            s0 = fmaf(a.z, x[16*k_+ 2], s0); s0 = fmaf(a.w, x[16*k_+ 3], s0);           \
            s1 = fmaf(b.x, x[16*k_+ 4], s1); s1 = fmaf(b.y, x[16*k_+ 5], s1);           \
            s1 = fmaf(b.z, x[16*k_+ 6], s1); s1 = fmaf(b.w, x[16*k_+ 7], s1);           \
            s2 = fmaf(c.x, x[16*k_+ 8], s2); s2 = fmaf(c.y, x[16*k_+ 9], s2);           \
            s2 = fmaf(c.z, x[16*k_+10], s2); s2 = fmaf(c.w, x[16*k_+11], s2);           \
            s3 = fmaf(d.x, x[16*k_+12], s3); s3 = fmaf(d.y, x[16*k_+13], s3);           \
            s3 = fmaf(d.z, x[16*k_+14], s3); s3 = fmaf(d.w, x[16*k_+15], s3);           \
        }                                                                               \
        OUT = (s0 + s1) + (s2 + s3);                                                    \
    } while (0)

    float dz, dr, dn;
    DOTX(32 + j, dz);
    DOTX(j, dr);
    DOTX(64 + j, dn);
#undef DOTX

    float* pp = g_proj + (size_t)link * 96;
    pp[j]             = dz + sb[32 + j] + sb[128 + j];
    pp[32 + 2*j]      = dr + sb[j] + sb[96 + j];
    pp[32 + 2*j + 1]  = dn + sb[64 + j];
}

// ---------------------------------------------------------------------------
// Path kernel (exact R6 version — known good): warp-per-path, lane = feature.
//  - h broadcast via per-warp shared staging + LDS.128
//  - hidden-side dots with packed fma.rn.f32x2 (weights pre-packed in regs)
// ---------------------------------------------------------------------------
#define NT_PATH 256
#define PATH_BLOCKS 592

__global__ void __launch_bounds__(NT_PATH, 2) path_kernel(
    const int* __restrict__ links,
    const float* __restrict__ Whh, const float* __restrict__ bhh)
{
    __shared__ float sH[2][NT_PATH];   // [hop parity][warp*32 + lane]

    const int lane = threadIdx.x & 31;
    const int wslot = threadIdx.x;               // warp*32 + lane
    const int wbase = threadIdx.x & ~31;         // warp*32
    const int warp_global = (blockIdx.x * (NT_PATH / 32)) + (threadIdx.x >> 5);
    const int n_warps = gridDim.x * (NT_PATH / 32);

    // Pre-packed weight pairs: Wz2[k] = (Wz[2k], Wz[2k+1]) etc.
    unsigned long long Wz2[16], Wr2[16], Wn2[16];
    {
        const float2* wz = (const float2*)(Whh + (size_t)(32 + lane) * 32);
        const float2* wr = (const float2*)(Whh + (size_t)lane * 32);
        const float2* wn = (const float2*)(Whh + (size_t)(64 + lane) * 32);
#pragma unroll
        for (int k = 0; k < 16; k++) {
            float2 a = wz[k]; PACKF2(Wz2[k], a.x, a.y);
            float2 b = wr[k]; PACKF2(Wr2[k], b.x, b.y);
            float2 c = wn[k]; PACKF2(Wn2[k], c.x, c.y);
        }
    }
    const float bn = bhh[64 + lane];

    for (int p = warp_global; p < NP; p += n_warps) {
        float h = g_path_state[(size_t)p * 32 + lane];
        int links8 = (lane < 8) ? links[(size_t)p * 8 + lane] : 0;

#pragma unroll
        for (int t = 0; t < PL; t++) {
            const int link = __shfl_sync(0xffffffffu, links8, t);
            const float* pp = g_proj + (size_t)link * 96;
            const float Zp = pp[lane];                               // 1 line
            const float2 RN = *(const float2*)(pp + 32 + 2 * lane);  // 2 lines

            // Stage h for warp-wide broadcast (double buffer -> 1 syncwarp/hop)
            const int par = t & 1;
            sH[par][wslot] = h;
            __syncwarp();
            const float4* hv4 = (const float4*)(&sH[par][wbase]);

            unsigned long long az2 = 0ull, ar2 = 0ull, an2 = 0ull;
#pragma unroll
            for (int kk = 0; kk < 8; kk++) {
                float4 hv = hv4[kk];                 // broadcast LDS.128
                unsigned long long h01, h23;
                PACKF2(h01, hv.x, hv.y);
                PACKF2(h23, hv.z, hv.w);
                FMAF2(az2, Wz2[2*kk],   h01, az2);
                FMAF2(az2, Wz2[2*kk+1], h23, az2);
                FMAF2(ar2, Wr2[2*kk],   h01, ar2);
                FMAF2(ar2, Wr2[2*kk+1], h23, ar2);
                FMAF2(an2, Wn2[2*kk],   h01, an2);
                FMAF2(an2, Wn2[2*kk+1], h23, an2);
            }
            float azl, azh, arl, arh, anl, anh;
            UNPACKF2(azl, azh, az2);
            UNPACKF2(arl, arh, ar2);
            UNPACKF2(anl, anh, an2);

            const float z = fsig(Zp + (azl + azh));
            const float r = fsig(RN.x + (arl + arh));
            const float n = ftanh(RN.y + r * ((anl + anh) + bn));
            h = fmaf(z, h - n, n);                   // h' = n + z*(h-n)
            atomicAdd(g_agg + (size_t)link * 32 + lane, h);   // 1 coalesced line
        }

        g_path_state[(size_t)p * 32 + lane] = h;
    }
}

// ---------------------------------------------------------------------------
// Fused link-update + next-round projection (R8).
// Warp-per-link, lane = feature j. No register arrays (spill-proof):
// dots via shfl broadcast of per-lane x/h; weights in shared TRANSPOSED.
//   sWT[k*192 + row]: rows [0:32)=lWih_r [32:64)=lWih_z [64:96)=lWih_n
//                     [96:128)=lWhh_r [128:160)=lWhh_z [160:192)=lWhh_n
//   sPT[k*96 + row]:  rows [0:32)=pWih_r [32:64)=pWih_z [64:96)=pWih_n
// After computing h' (link GRU), computes the path-GRU input projection of h'
// and writes g_proj — replacing the standalone proj kernel for rounds >= 1.
// ---------------------------------------------------------------------------
#define NT_LINKF 256

__global__ void __launch_bounds__(NT_LINKF) linkfuse_kernel(
    const float* __restrict__ lWih, const float* __restrict__ lWhh,
    const float* __restrict__ lbih, const float* __restrict__ lbhh,
    const float* __restrict__ pWih, const float* __restrict__ pbih,
    const float* __restrict__ pbhh)
{
    __shared__ float sWT[32 * 192];   // 24 KB  (link GRU weights, transposed)
    __shared__ float sPT[32 * 96];    // 12 KB  (path Wih, transposed)
    __shared__ float sb[192];         // link biases
    __shared__ float sbp[192];        // path biases (bih, bhh)

    const int tid = threadIdx.x;
    for (int i = tid; i < 3072; i += NT_LINKF) {
        const int row = i >> 5, k = i & 31;
        sWT[k * 192 + row]      = lWih[i];
        sWT[k * 192 + 96 + row] = lWhh[i];
        sPT[k * 96 + row]       = pWih[i];
    }
    if (tid < 96) {
        sb[tid] = lbih[tid];  sb[96 + tid] = lbhh[tid];
        sbp[tid] = pbih[tid]; sbp[96 + tid] = pbhh[tid];
    }
    __syncthreads();

    const int gid = blockIdx.x * NT_LINKF + tid;
    const int link = gid >> 5;
    const int j = gid & 31;
    if (link >= NL) return;

    const float x = g_agg[(size_t)link * 32 + j];          // coalesced
    const float h = g_link_state[(size_t)link * 32 + j];   // coalesced

    // ---- link GRU: six dots via shfl broadcast ----
    float dr = 0.f, dz = 0.f, dn = 0.f;   // input-side (x)
    float er = 0.f, ez = 0.f, en = 0.f;   // hidden-side (h)
#pragma unroll
    for (int k = 0; k < 32; k++) {
        const float xk = __shfl_sync(0xffffffffu, x, k);
        const float hk = __shfl_sync(0xffffffffu, h, k);
        const float* w = sWT + k * 192;
        dr = fmaf(w[j],       xk, dr);
        dz = fmaf(w[32 + j],  xk, dz);
        dn = fmaf(w[64 + j],  xk, dn);
        er = fmaf(w[96 + j],  hk, er);
        ez = fmaf(w[128 + j], hk, ez);
        en = fmaf(w[160 + j], hk, en);
    }

    const float z = fsig(dz + sb[32 + j] + ez + sb[128 + j]);
    const float r = fsig(dr + sb[j] + er + sb[96 + j]);
    const float n = ftanh(dn + sb[64 + j] + r * (en + sb[160 + j]));
    const float hn = fmaf(z, h - n, n);

    g_link_state[(size_t)link * 32 + j] = hn;   // coalesced
    g_agg[(size_t)link * 32 + j] = 0.0f;        // clear for next round

    // ---- fused projection of NEW link state for next path round ----
    float pz = 0.f, pr = 0.f, pn = 0.f;
#pragma unroll
    for (int k = 0; k < 32; k++) {
        const float hk = __shfl_sync(0xffffffffu, hn, k);
        const float* w = sPT + k * 96;
        pr = fmaf(w[j],      hk, pr);
        pz = fmaf(w[32 + j], hk, pz);
        pn = fmaf(w[64 + j], hk, pn);
    }

    float* pp = g_proj + (size_t)link * 96;
    pp[j]            = pz + sbp[32 + j] + sbp[128 + j];
    pp[32 + 2*j]     = pr + sbp[j] + sbp[96 + j];
    pp[32 + 2*j + 1] = pn + sbp[64 + j];
}

// ---------------------------------------------------------------------------
// Readout MLP: 32 -> relu 8 -> relu 8 -> 1
// ---------------------------------------------------------------------------
__global__ void __launch_bounds__(128) readout_kernel(
    const float* __restrict__ W1, const float* __restrict__ b1,
    const float* __restrict__ W2, const float* __restrict__ b2,
    const float* __restrict__ W3, const float* __restrict__ b3,
    float* __restrict__ out)
{
    __shared__ float sW1[256], sW2[64], sW3[8], sb1[8], sb2[8], sb3;
    int tid = threadIdx.x;
    for (int i = tid; i < 256; i += 128) sW1[i] = W1[i];
    if (tid < 64) sW2[tid] = W2[tid];
    if (tid < 8) { sW3[tid] = W3[tid]; sb1[tid] = b1[tid]; sb2[tid] = b2[tid]; }
    if (tid == 0) sb3 = b3[0];
    __syncthreads();

    int p = blockIdx.x * 128 + tid;
    if (p >= NP) return;

    float x[32];
    const float4* hp = (const float4*)(g_path_state + (size_t)p * 32);
#pragma unroll
    for (int k = 0; k < 8; k++) {
        float4 v = hp[k];
        x[4*k] = v.x; x[4*k+1] = v.y; x[4*k+2] = v.z; x[4*k+3] = v.w;
    }
    float y[8];
#pragma unroll
    for (int j = 0; j < 8; j++) {
        float s = sb1[j];
#pragma unroll
        for (int k = 0; k < 32; k++) s = fmaf(sW1[j * 32 + k], x[k], s);
        y[j] = fmaxf(s, 0.0f);
    }
    float y2[8];
#pragma unroll
    for (int j = 0; j < 8; j++) {
        float s = sb2[j];
#pragma unroll
        for (int k = 0; k < 8; k++) s = fmaf(sW2[j * 8 + k], y[k], s);
        y2[j] = fmaxf(s, 0.0f);
    }
    float s = sb3;
#pragma unroll
    for (int k = 0; k < 8; k++) s = fmaf(sW3[k], y2[k], s);
    out[p] = s;
}

// ---------------------------------------------------------------------------
extern "C" void kernel_launch(void* const* d_in, const int* in_sizes, int n_in,
                              void* d_out, int out_size)
{
    const int*   links = (const int*)d_in[0];
    // d_in[1]=paths, d_in[2]=seqs: layout is paths=repeat, seqs=tile -> hop(p,t)=links[8p+t]
    const float* cap   = (const float*)d_in[3];
    const float* bw    = (const float*)d_in[4];
    const float* pWih  = (const float*)d_in[5];
    const float* pWhh  = (const float*)d_in[6];
    const float* pbih  = (const float*)d_in[7];
    const float* pbhh  = (const float*)d_in[8];
    const float* lWih  = (const float*)d_in[9];
    const float* lWhh  = (const float*)d_in[10];
    const float* lbih  = (const float*)d_in[11];
    const float* lbhh  = (const float*)d_in[12];
    const float* W1    = (const float*)d_in[13];
    const float* b1    = (const float*)d_in[14];
    const float* W2    = (const float*)d_in[15];
    const float* b2    = (const float*)d_in[16];
    const float* W3    = (const float*)d_in[17];
    const float* b3    = (const float*)d_in[18];
    float* out = (float*)d_out;

    init_kernel<<<(NP * HH + 255) / 256, 256>>>(cap, bw);

    const int proj_blocks = (NL * 32 + NT_PROJ - 1) / NT_PROJ;
    const int linkf_blocks = (NL * 32 + NT_LINKF - 1) / NT_LINKF;

    // Round-0 projection from the initial link state
    proj_kernel<<<proj_blocks, NT_PROJ>>>(pWih, pbih, pbhh);

    for (int r = 0; r < NROUNDS; r++) {
        path_kernel<<<PATH_BLOCKS, NT_PATH>>>(links, pWhh, pbhh);
        if (r < NROUNDS - 1)  // final link update is dead code (readout uses path_state)
            linkfuse_kernel<<<linkf_blocks, NT_LINKF>>>(lWih, lWhh, lbih, lbhh,
                                                        pWih, pbih, pbhh);
    }
    readout_kernel<<<(NP + 127) / 128, 128>>>(W1, b1, W2, b2, W3, b3, out);
}

// round 10
// speedup vs baseline: 1.1987x; 1.0845x over previous
#include <cuda_runtime.h>
#include <math.h>

#define NL 10000
#define NP 100000
#define PL 8
#define HH 32
#define NROUNDS 8

// Scratch state (no allocations allowed)
__device__ __align__(256) float g_link_state[NL * HH];
__device__ __align__(256) float g_path_state[NP * HH];
__device__ __align__(256) float g_agg[NL * HH];
// Per-link input-side projection, biases folded.
// Layout per link (96 floats): [0:32) = Z_j ; [32:96) = interleaved (R_j, N_j) pairs.
__device__ __align__(256) float g_proj[NL * 96];

__device__ __forceinline__ float sigf(float v) { return 1.0f / (1.0f + expf(-v)); }

// Fast activations. __expf error ~2^-21 rel; far inside 1e-3 budget.
__device__ __forceinline__ float fsig(float v) {
    return __fdividef(1.0f, 1.0f + __expf(-v));
}
__device__ __forceinline__ float ftanh(float v) {
    float e = __expf(-2.0f * fabsf(v));
    float t = __fdividef(1.0f - e, 1.0f + e);
    return copysignf(t, v);
}

// Packed fp32x2 helpers (sm_100+). Bit-exact fp32 FMA semantics, 2 lanes/instr.
#define PACKF2(out, lo, hi) \
    asm("mov.b64 %0, {%1, %2};" : "=l"(out) : "r"(__float_as_uint(lo)), "r"(__float_as_uint(hi)))
#define UNPACKF2(lo, hi, in) \
    do { unsigned int _ul, _uh; \
         asm("mov.b64 {%0, %1}, %2;" : "=r"(_ul), "=r"(_uh) : "l"(in)); \
         lo = __uint_as_float(_ul); hi = __uint_as_float(_uh); } while (0)
#define FMAF2(d, a, b, c) \
    asm("fma.rn.f32x2 %0, %1, %2, %3;" : "=l"(d) : "l"(a), "l"(b), "l"(c))

// ---------------------------------------------------------------------------
// Init
// ---------------------------------------------------------------------------
__global__ void init_kernel(const float* __restrict__ cap, const float* __restrict__ bw) {
    int i = blockIdx.x * blockDim.x + threadIdx.x;
    if (i < NL * HH) {
        g_link_state[i] = ((i & 31) == 0) ? cap[i >> 5] : 0.0f;
        g_agg[i] = 0.0f;
    }
    if (i < NP * HH) {
        g_path_state[i] = ((i & 31) == 0) ? bw[i >> 5] : 0.0f;
    }
}

// ---------------------------------------------------------------------------
// Projection kernel: proj[link] = Wih @ link_state[link] with biases folded.
// One warp per link, lane j computes (Z_j, R_j, N_j).
// ---------------------------------------------------------------------------
#define NT_PROJ 256

__global__ void __launch_bounds__(NT_PROJ) proj_kernel(
    const float* __restrict__ Wih, const float* __restrict__ bih,
    const float* __restrict__ bhh)
{
    __shared__ float sWih[3072];
    __shared__ float sb[192];
    const int tid = threadIdx.x;
    for (int i = tid; i < 3072; i += NT_PROJ) sWih[i] = Wih[i];
    if (tid < 96) { sb[tid] = bih[tid]; sb[96 + tid] = bhh[tid]; }
    __syncthreads();

    const int gid = blockIdx.x * NT_PROJ + tid;
    const int link = gid >> 5;
    const int j = gid & 31;
    if (link >= NL) return;

    float x[32];
    {
        const float4* xp = (const float4*)(g_link_state + (size_t)link * 32);
#pragma unroll
        for (int k = 0; k < 8; k++) {
            float4 v = xp[k];
            x[4*k] = v.x; x[4*k+1] = v.y; x[4*k+2] = v.z; x[4*k+3] = v.w;
        }
    }

#define DOTX(ROW, OUT)                                                                  \
    do {                                                                                \
        const float4* wi_ = (const float4*)(sWih + (ROW) * 32);                         \
        float s0 = 0.f, s1 = 0.f, s2 = 0.f, s3 = 0.f;                                   \
        _Pragma("unroll")                                                               \
        for (int k_ = 0; k_ < 2; k_++) {                                                \
            float4 a = wi_[4*k_+0], b = wi_[4*k_+1], c = wi_[4*k_+2], d = wi_[4*k_+3];  \
            s0 = fmaf(a.x, x[16*k_+ 0], s0); s0 = fmaf(a.y, x[16*k_+ 1], s0);           \
            s0 = fmaf(a.z, x[16*k_+ 2], s0); s0 = fmaf(a.w, x[16*k_+ 3], s0);           \
            s1 = fmaf(b.x, x[16*k_+ 4], s1); s1 = fmaf(b.y, x[16*k_+ 5], s1);           \
            s1 = fmaf(b.z, x[16*k_+ 6], s1); s1 = fmaf(b.w, x[16*k_+ 7], s1);           \
            s2 = fmaf(c.x, x[16*k_+ 8], s2); s2 = fmaf(c.y, x[16*k_+ 9], s2);           \
            s2 = fmaf(c.z, x[16*k_+10], s2); s2 = fmaf(c.w, x[16*k_+11], s2);           \
            s3 = fmaf(d.x, x[16*k_+12], s3); s3 = fmaf(d.y, x[16*k_+13], s3);           \
            s3 = fmaf(d.z, x[16*k_+14], s3); s3 = fmaf(d.w, x[16*k_+15], s3);           \
        }                                                                               \
        OUT = (s0 + s1) + (s2 + s3);                                                    \
    } while (0)

    float dz, dr, dn;
    DOTX(32 + j, dz);
    DOTX(j, dr);
    DOTX(64 + j, dn);
#undef DOTX

    float* pp = g_proj + (size_t)link * 96;
    pp[j]             = dz + sb[32 + j] + sb[128 + j];
    pp[32 + 2*j]      = dr + sb[j] + sb[96 + j];
    pp[32 + 2*j + 1]  = dn + sb[64 + j];
}

// ---------------------------------------------------------------------------
// Path kernel (R9/R10): 2 paths per warp, lane = feature.
//  - both paths share the 96 register-resident packed weight pairs
//  - 6 independent FMA2 chains per hop (double the ILP of R6)
//  - h staged PRE-PACKED (even lanes store (h2k,h2k+1) pairs) -> no per-hop packs
//  - NT=192, launch_bounds(192,2): reg cap 170 -> no spill risk
// ---------------------------------------------------------------------------
#define NT_PATH 192
#define PATH_BLOCKS 296

__global__ void __launch_bounds__(NT_PATH, 2) path_kernel(
    const int* __restrict__ links,
    const float* __restrict__ Whh, const float* __restrict__ bhh)
{
    __shared__ __align__(16) unsigned long long sA[2][NT_PATH / 2];  // path0 packed h
    __shared__ __align__(16) unsigned long long sB[2][NT_PATH / 2];  // path1 packed h

    const int lane = threadIdx.x & 31;
    const int wbase = threadIdx.x & ~31;
    const int warp_global = (blockIdx.x * (NT_PATH / 32)) + (threadIdx.x >> 5);
    const int n_warps = gridDim.x * (NT_PATH / 32);
    const int pslot = (wbase >> 1) + (lane >> 1);

    // Pre-packed weight pairs: Wz2[k] = (Wz[2k], Wz[2k+1]) etc.
    unsigned long long Wz2[16], Wr2[16], Wn2[16];
    {
        const float2* wz = (const float2*)(Whh + (size_t)(32 + lane) * 32);
        const float2* wr = (const float2*)(Whh + (size_t)lane * 32);
        const float2* wn = (const float2*)(Whh + (size_t)(64 + lane) * 32);
#pragma unroll
        for (int k = 0; k < 16; k++) {
            float2 a = wz[k]; PACKF2(Wz2[k], a.x, a.y);
            float2 b = wr[k]; PACKF2(Wr2[k], b.x, b.y);
            float2 c = wn[k]; PACKF2(Wn2[k], c.x, c.y);
        }
    }
    const float bn = bhh[64 + lane];

    for (int pi = warp_global; pi < NP / 2; pi += n_warps) {
        const int p0 = pi * 2;
        float h0 = g_path_state[(size_t)p0 * 32 + lane];
        float h1 = g_path_state[(size_t)p0 * 32 + 32 + lane];
        // lane<8: path0 hop ids; lane 8..15: path1 hop ids (contiguous in links)
        int links16 = (lane < 16) ? links[(size_t)p0 * 8 + lane] : 0;

#pragma unroll
        for (int t = 0; t < PL; t++) {
            const int link0 = __shfl_sync(0xffffffffu, links16, t);
            const int link1 = __shfl_sync(0xffffffffu, links16, 8 + t);
            const float* pp0 = g_proj + (size_t)link0 * 96;
            const float* pp1 = g_proj + (size_t)link1 * 96;
            const float  Zp0 = pp0[lane];
            const float2 RN0 = *(const float2*)(pp0 + 32 + 2 * lane);
            const float  Zp1 = pp1[lane];
            const float2 RN1 = *(const float2*)(pp1 + 32 + 2 * lane);

            // Stage packed h pairs (even lanes store (h_j, h_{j+1}))
            const int par = t & 1;
            const float h0n = __shfl_down_sync(0xffffffffu, h0, 1);
            const float h1n = __shfl_down_sync(0xffffffffu, h1, 1);
            unsigned long long q0, q1;
            PACKF2(q0, h0, h0n);
            PACKF2(q1, h1, h1n);
            if (!(lane & 1)) { sA[par][pslot] = q0; sB[par][pslot] = q1; }
            __syncwarp();

            const ulonglong2* hv0 = (const ulonglong2*)&sA[par][wbase >> 1];
            const ulonglong2* hv1 = (const ulonglong2*)&sB[par][wbase >> 1];
            unsigned long long az0 = 0ull, ar0 = 0ull, an0 = 0ull;
            unsigned long long az1 = 0ull, ar1 = 0ull, an1 = 0ull;
#pragma unroll
            for (int kk = 0; kk < 8; kk++) {
                const ulonglong2 u0 = hv0[kk];   // broadcast LDS.128: 2 packed pairs
                const ulonglong2 u1 = hv1[kk];
                FMAF2(az0, Wz2[2*kk],   u0.x, az0);
                FMAF2(az0, Wz2[2*kk+1], u0.y, az0);
                FMAF2(ar0, Wr2[2*kk],   u0.x, ar0);
                FMAF2(ar0, Wr2[2*kk+1], u0.y, ar0);
                FMAF2(an0, Wn2[2*kk],   u0.x, an0);
                FMAF2(an0, Wn2[2*kk+1], u0.y, an0);
                FMAF2(az1, Wz2[2*kk],   u1.x, az1);
                FMAF2(az1, Wz2[2*kk+1], u1.y, az1);
                FMAF2(ar1, Wr2[2*kk],   u1.x, ar1);
                FMAF2(ar1, Wr2[2*kk+1], u1.y, ar1);
                FMAF2(an1, Wn2[2*kk],   u1.x, an1);
                FMAF2(an1, Wn2[2*kk+1], u1.y, an1);
            }

            {
                float al, ah, bl, bh, cl, ch;
                UNPACKF2(al, ah, az0);
                UNPACKF2(bl, bh, ar0);
                UNPACKF2(cl, ch, an0);
                const float z = fsig(Zp0 + (al + ah));
                const float r = fsig(RN0.x + (bl + bh));
                const float n = ftanh(RN0.y + r * ((cl + ch) + bn));
                h0 = fmaf(z, h0 - n, n);
                atomicAdd(g_agg + (size_t)link0 * 32 + lane, h0);
            }
            {
                float al, ah, bl, bh, cl, ch;
                UNPACKF2(al, ah, az1);
                UNPACKF2(bl, bh, ar1);
                UNPACKF2(cl, ch, an1);
                const float z = fsig(Zp1 + (al + ah));
                const float r = fsig(RN1.x + (bl + bh));
                const float n = ftanh(RN1.y + r * ((cl + ch) + bn));
                h1 = fmaf(z, h1 - n, n);
                atomicAdd(g_agg + (size_t)link1 * 32 + lane, h1);
            }
        }

        g_path_state[(size_t)p0 * 32 + lane] = h0;
        g_path_state[(size_t)p0 * 32 + 32 + lane] = h1;
    }
}

// ---------------------------------------------------------------------------
// Link kernel (exact R6 version — known good 26us): one GRU step per link.
// input x = agg, hidden h = link_state. Zeroes agg for the next round.
// ---------------------------------------------------------------------------
#define NT_LINK 64

#define DOT2(ROW_I, ROW_H, OUT_SI, OUT_SH)                                              \
    do {                                                                                \
        const float4* wi_ = (const float4*)(sWih + (ROW_I) * 32);                       \
        const float4* wh_ = (const float4*)(sWhh + (ROW_H) * 32);                       \
        float si0 = 0.f, si1 = 0.f, sh0 = 0.f, sh1 = 0.f;                               \
        _Pragma("unroll")                                                               \
        for (int k_ = 0; k_ < 8; k_ += 2) {                                             \
            float4 a = wi_[k_], b = wh_[k_], c = wi_[k_ + 1], d = wh_[k_ + 1];          \
            si0 = fmaf(a.x, x[4*k_+0], si0); si0 = fmaf(a.y, x[4*k_+1], si0);           \
            si0 = fmaf(a.z, x[4*k_+2], si0); si0 = fmaf(a.w, x[4*k_+3], si0);           \
            sh0 = fmaf(b.x, h[4*k_+0], sh0); sh0 = fmaf(b.y, h[4*k_+1], sh0);           \
            sh0 = fmaf(b.z, h[4*k_+2], sh0); sh0 = fmaf(b.w, h[4*k_+3], sh0);           \
            si1 = fmaf(c.x, x[4*k_+4], si1); si1 = fmaf(c.y, x[4*k_+5], si1);           \
            si1 = fmaf(c.z, x[4*k_+6], si1); si1 = fmaf(c.w, x[4*k_+7], si1);           \
            sh1 = fmaf(d.x, h[4*k_+4], sh1); sh1 = fmaf(d.y, h[4*k_+5], sh1);           \
            sh1 = fmaf(d.z, h[4*k_+6], sh1); sh1 = fmaf(d.w, h[4*k_+7], sh1);           \
        }                                                                               \
        OUT_SI = si0 + si1; OUT_SH = sh0 + sh1;                                         \
    } while (0)

__global__ void __launch_bounds__(NT_LINK) link_kernel(
    const float* __restrict__ Wih, const float* __restrict__ Whh,
    const float* __restrict__ bih, const float* __restrict__ bhh)
{
    __shared__ float sWih[3072];
    __shared__ float sWhh[3072];
    __shared__ float sb[192];
    __shared__ float sZ[32 * NT_LINK];
    __shared__ float sN[32 * NT_LINK];

    const int tid = threadIdx.x;
    for (int i = tid; i < 3072; i += NT_LINK) { sWih[i] = Wih[i]; sWhh[i] = Whh[i]; }
    for (int i = tid; i < 96; i += NT_LINK) { sb[i] = bih[i]; sb[96 + i] = bhh[i]; }
    __syncthreads();

    const int l = blockIdx.x * NT_LINK + tid;
    if (l >= NL) return;

    float h[32], x[32];
    {
        const float4* hp = (const float4*)(g_link_state + (size_t)l * 32);
        const float4* xp = (const float4*)(g_agg + (size_t)l * 32);
#pragma unroll
        for (int k = 0; k < 8; k++) {
            float4 v = hp[k];
            h[4*k] = v.x; h[4*k+1] = v.y; h[4*k+2] = v.z; h[4*k+3] = v.w;
            float4 u = xp[k];
            x[4*k] = u.x; x[4*k+1] = u.y; x[4*k+2] = u.z; x[4*k+3] = u.w;
        }
    }

    for (int j = 0; j < 32; j++) {
        float si, sh;
        DOT2(32 + j, 32 + j, si, sh);
        sZ[j * NT_LINK + tid] = sigf(si + sb[32 + j] + sh + sb[128 + j]);
    }
    for (int j = 0; j < 32; j++) {
        float sir, shr;
        DOT2(j, j, sir, shr);
        float r = sigf(sir + sb[j] + shr + sb[96 + j]);
        float sin_, shn;
        DOT2(64 + j, 64 + j, sin_, shn);
        float n = tanhf(sin_ + sb[64 + j] + r * (shn + sb[160 + j]));
        sN[j * NT_LINK + tid] = n;
    }

    float4* hp = (float4*)(g_link_state + (size_t)l * 32);
    float4* ap = (float4*)(g_agg + (size_t)l * 32);
#pragma unroll
    for (int k = 0; k < 8; k++) {
        float4 v;
        {
            int j = 4 * k;
            float z0 = sZ[(j+0) * NT_LINK + tid], n0 = sN[(j+0) * NT_LINK + tid];
            float z1 = sZ[(j+1) * NT_LINK + tid], n1 = sN[(j+1) * NT_LINK + tid];
            float z2 = sZ[(j+2) * NT_LINK + tid], n2 = sN[(j+2) * NT_LINK + tid];
            float z3 = sZ[(j+3) * NT_LINK + tid], n3 = sN[(j+3) * NT_LINK + tid];
            v.x = fmaf(z0, h[j+0] - n0, n0);
            v.y = fmaf(z1, h[j+1] - n1, n1);
            v.z = fmaf(z2, h[j+2] - n2, n2);
            v.w = fmaf(z3, h[j+3] - n3, n3);
        }
        hp[k] = v;
        ap[k] = make_float4(0.f, 0.f, 0.f, 0.f);  // clear agg for next round
    }
}

// ---------------------------------------------------------------------------
// Readout MLP: 32 -> relu 8 -> relu 8 -> 1
// ---------------------------------------------------------------------------
__global__ void __launch_bounds__(128) readout_kernel(
    const float* __restrict__ W1, const float* __restrict__ b1,
    const float* __restrict__ W2, const float* __restrict__ b2,
    const float* __restrict__ W3, const float* __restrict__ b3,
    float* __restrict__ out)
{
    __shared__ float sW1[256], sW2[64], sW3[8], sb1[8], sb2[8], sb3;
    int tid = threadIdx.x;
    for (int i = tid; i < 256; i += 128) sW1[i] = W1[i];
    if (tid < 64) sW2[tid] = W2[tid];
    if (tid < 8) { sW3[tid] = W3[tid]; sb1[tid] = b1[tid]; sb2[tid] = b2[tid]; }
    if (tid == 0) sb3 = b3[0];
    __syncthreads();

    int p = blockIdx.x * 128 + tid;
    if (p >= NP) return;

    float x[32];
    const float4* hp = (const float4*)(g_path_state + (size_t)p * 32);
#pragma unroll
    for (int k = 0; k < 8; k++) {
        float4 v = hp[k];
        x[4*k] = v.x; x[4*k+1] = v.y; x[4*k+2] = v.z; x[4*k+3] = v.w;
    }
    float y[8];
#pragma unroll
    for (int j = 0; j < 8; j++) {
        float s = sb1[j];
#pragma unroll
        for (int k = 0; k < 32; k++) s = fmaf(sW1[j * 32 + k], x[k], s);
        y[j] = fmaxf(s, 0.0f);
    }
    float y2[8];
#pragma unroll
    for (int j = 0; j < 8; j++) {
        float s = sb2[j];
#pragma unroll
        for (int k = 0; k < 8; k++) s = fmaf(sW2[j * 8 + k], y[k], s);
        y2[j] = fmaxf(s, 0.0f);
    }
    float s = sb3;
#pragma unroll
    for (int k = 0; k < 8; k++) s = fmaf(sW3[k], y2[k], s);
    out[p] = s;
}

// ---------------------------------------------------------------------------
extern "C" void kernel_launch(void* const* d_in, const int* in_sizes, int n_in,
                              void* d_out, int out_size)
{
    const int*   links = (const int*)d_in[0];
    // d_in[1]=paths, d_in[2]=seqs: layout is paths=repeat, seqs=tile -> hop(p,t)=links[8p+t]
    const float* cap   = (const float*)d_in[3];
    const float* bw    = (const float*)d_in[4];
    const float* pWih  = (const float*)d_in[5];
    const float* pWhh  = (const float*)d_in[6];
    const float* pbih  = (const float*)d_in[7];
    const float* pbhh  = (const float*)d_in[8];
    const float* lWih  = (const float*)d_in[9];
    const float* lWhh  = (const float*)d_in[10];
    const float* lbih  = (const float*)d_in[11];
    const float* lbhh  = (const float*)d_in[12];
    const float* W1    = (const float*)d_in[13];
    const float* b1    = (const float*)d_in[14];
    const float* W2    = (const float*)d_in[15];
    const float* b2    = (const float*)d_in[16];
    const float* W3    = (const float*)d_in[17];
    const float* b3    = (const float*)d_in[18];
    float* out = (float*)d_out;

    init_kernel<<<(NP * HH + 255) / 256, 256>>>(cap, bw);

    const int link_blocks = (NL + NT_LINK - 1) / NT_LINK;
    const int proj_blocks = (NL * 32 + NT_PROJ - 1) / NT_PROJ;
    for (int r = 0; r < NROUNDS; r++) {
        proj_kernel<<<proj_blocks, NT_PROJ>>>(pWih, pbih, pbhh);
        path_kernel<<<PATH_BLOCKS, NT_PATH>>>(links, pWhh, pbhh);
        if (r < NROUNDS - 1)  // final link update is dead code (readout uses path_state)
            link_kernel<<<link_blocks, NT_LINK>>>(lWih, lWhh, lbih, lbhh);
    }
    readout_kernel<<<(NP + 127) / 128, 128>>>(W1, b1, W2, b2, W3, b3, out);
}